// round 9
// baseline (speedup 1.0000x reference)
#include <cuda_runtime.h>
#include <cuda_fp16.h>
#include <cstdint>
#include <math.h>

// ---------------- problem constants ----------------
#define B_   4
#define CIN  128
#define COUT 256
#define H_   128
#define W_   256
#define HW   (H_ * W_)              // 32768
#define TILE_M 128                  // pixels per CTA
#define NTILES (B_ * HW / TILE_M)   // 1024
#define NTHREADS 640                // 16 MMA warps + 4 gather warps

// ---------------- device scratch ----------------
__device__ __half g_xh[(size_t)B_ * HW * CIN];       // 32 MB (B, HW, Cin) fp16
__device__ unsigned char g_Wf16[9 * 65536];          // per tap: 256 co x 256B (128 fp16), swizzled
__device__ int4   g_tabI[9 * HW];                    // gather indices (uint2 units into g_xh)
__device__ float4 g_tabW[9 * HW];                    // bilinear weights (edge-zeroed)

// ---------------- smem layout (1024-aligned base) ----------------
#define SM_A0   0            // 128 rows x 256B = 32KB
#define SM_A1   32768        // 32KB
#define SM_W0   65536        // 64KB
#define SM_W1   131072       // 64KB
#define SM_BIAS 196608       // 1KB
#define SM_TOTAL (197632 + 1024)
// epilogue reuses [0, 128KB) as Dsm[co][px] fp32

__device__ __forceinline__ uint32_t bswz(uint32_t row, uint32_t col) {
    return col ^ ((row & 7u) << 4);
}

__device__ __forceinline__ uint32_t smem_u32(const void* p) {
    uint32_t a;
    asm("{ .reg .u64 t; cvta.to.shared.u64 t, %1; cvt.u32.u64 %0, t; }" : "=r"(a) : "l"(p));
    return a;
}

__device__ __forceinline__ void ldm_x4(uint32_t& r0, uint32_t& r1, uint32_t& r2, uint32_t& r3,
                                       uint32_t addr) {
    asm volatile("ldmatrix.sync.aligned.m8n8.x4.shared.b16 {%0,%1,%2,%3}, [%4];"
                 : "=r"(r0), "=r"(r1), "=r"(r2), "=r"(r3) : "r"(addr));
}

__device__ __forceinline__ void mma_16816(float& c0, float& c1, float& c2, float& c3,
                                          uint32_t a0, uint32_t a1, uint32_t a2, uint32_t a3,
                                          uint32_t b0, uint32_t b1) {
    asm volatile(
        "mma.sync.aligned.m16n8k16.row.col.f32.f16.f16.f32 "
        "{%0,%1,%2,%3}, {%4,%5,%6,%7}, {%8,%9}, {%0,%1,%2,%3};"
        : "+f"(c0), "+f"(c1), "+f"(c2), "+f"(c3)
        : "r"(a0), "r"(a1), "r"(a2), "r"(a3), "r"(b0), "r"(b1));
}

__device__ __forceinline__ void cp_async16(uint32_t dst, const void* src) {
    asm volatile("cp.async.cg.shared.global [%0], [%1], 16;" :: "r"(dst), "l"(src) : "memory");
}
__device__ __forceinline__ void cp_commit() {
    asm volatile("cp.async.commit_group;" ::: "memory");
}
__device__ __forceinline__ void cp_wait0() {
    asm volatile("cp.async.wait_group 0;" ::: "memory");
}

// stage a 64KB pre-swizzled W block with the 4 gather warps (128 threads)
__device__ __forceinline__ void stageW_async_gw(uint32_t smem_dst, const unsigned char* src,
                                                int tidg) {
#pragma unroll
    for (int i = 0; i < 32; ++i) {
        cp_async16(smem_dst + i * 2048 + tidg * 16, src + i * 2048 + tidg * 16);
    }
}

// ---------------------------------------------------------------------------
// Kernel 1: transpose+convert x (B, Cin, H, W) fp32 -> g_xh (B, HW, Cin) fp16
// ---------------------------------------------------------------------------
__global__ void transpose_x_kernel(const float* __restrict__ x) {
    __shared__ float tile[32][33];
    const int b    = blockIdx.z;
    const int cin0 = blockIdx.y * 32;
    const int p0   = blockIdx.x * 32;
    const int tx = threadIdx.x, ty = threadIdx.y;   // 32 x 8
#pragma unroll
    for (int j = 0; j < 4; ++j)
        tile[ty + 8 * j][tx] = x[((size_t)b * CIN + (cin0 + ty + 8 * j)) * HW + (p0 + tx)];
    __syncthreads();
#pragma unroll
    for (int j = 0; j < 4; ++j)
        g_xh[((size_t)b * HW + (p0 + ty + 8 * j)) * CIN + (cin0 + tx)] =
            __float2half(tile[tx][ty + 8 * j]);
}

// ---------------------------------------------------------------------------
// Kernel 2: weight prep -> fp16 per tap, 256 co rows x 128 fp16, swizzled
// ---------------------------------------------------------------------------
__global__ void weight_prep_f16_kernel(const float* __restrict__ wsrc) {
    const int idx = blockIdx.x * 256 + threadIdx.x;   // < 9*256*128
    if (idx >= 9 * 256 * 128) return;
    const int cin = idx & 127;
    const int co  = (idx >> 7) & 255;
    const int t   = idx >> 15;
    const float v = wsrc[(co * CIN + cin) * 9 + t];
    const uint32_t off = (uint32_t)co * 256 + bswz(co, (uint32_t)cin * 2);
    *(__half*)(g_Wf16 + (size_t)t * 65536 + off) = __float2half(v);
}

// ---------------------------------------------------------------------------
// Kernel 2b: grid prep -> clamped gather indices + edge-zeroed weights
// ---------------------------------------------------------------------------
__global__ void grid_prep_kernel(const float* __restrict__ gridp) {
    const int idx = blockIdx.x * 256 + threadIdx.x;   // < 9*HW
    if (idx >= 9 * HW) return;
    const int p = idx & (HW - 1);
    const int t = idx >> 15;
    const int h = p >> 8;
    const int w = p & 255;
    const int r = t / 3;
    const int c = t - r * 3;

    const int gi = (h * 3 + r) * (W_ * 3) + (w * 3 + c);
    const float gx = gridp[2 * gi + 0];
    const float gy = gridp[2 * gi + 1];

    const float ix = ((gx + 1.0f) * (float)W_ - 1.0f) * 0.5f;
    const float iy = ((gy + 1.0f) * (float)H_ - 1.0f) * 0.5f;
    const float x0f = floorf(ix), y0f = floorf(iy);
    const float fx = ix - x0f, fy = iy - y0f;
    const int xx0 = (int)x0f, yy0 = (int)y0f;
    const int xx1 = xx0 + 1, yy1 = yy0 + 1;

    float w00 = (1.0f - fx) * (1.0f - fy);
    float w10 = fx * (1.0f - fy);
    float w01 = (1.0f - fx) * fy;
    float w11 = fx * fy;
    if (xx0 < 0 || xx0 >= W_) { w00 = 0.0f; w01 = 0.0f; }
    if (xx1 < 0 || xx1 >= W_) { w10 = 0.0f; w11 = 0.0f; }
    if (yy0 < 0 || yy0 >= H_) { w00 = 0.0f; w10 = 0.0f; }
    if (yy1 < 0 || yy1 >= H_) { w01 = 0.0f; w11 = 0.0f; }

    const int xi0 = min(max(xx0, 0), W_ - 1);
    const int xi1 = min(max(xx1, 0), W_ - 1);
    const int yi0 = min(max(yy0, 0), H_ - 1);
    const int yi1 = min(max(yy1, 0), H_ - 1);

    int4 e;
    e.x = (yi0 * W_ + xi0) * 32;
    e.y = (yi0 * W_ + xi1) * 32;
    e.z = (yi1 * W_ + xi0) * 32;
    e.w = (yi1 * W_ + xi1) * 32;
    g_tabI[idx] = e;
    g_tabW[idx] = make_float4(w00, w10, w01, w11);
}

// ---------------------------------------------------------------------------
// gather body for one pixel (blend 4 corners -> fp16 pair, swizzled STS)
// ---------------------------------------------------------------------------
__device__ __forceinline__ void gather_one(const uint2* __restrict__ xh2,
                                           char* __restrict__ abuf,
                                           const int4 e, const float4 wv,
                                           int pp, int lane) {
    const uint2 u00 = __ldg(xh2 + e.x + lane);
    const uint2 u10 = __ldg(xh2 + e.y + lane);
    const uint2 u01 = __ldg(xh2 + e.z + lane);
    const uint2 u11 = __ldg(xh2 + e.w + lane);

    const float2 a00 = __half22float2(*(const __half2*)&u00.x);
    const float2 b00 = __half22float2(*(const __half2*)&u00.y);
    const float2 a10 = __half22float2(*(const __half2*)&u10.x);
    const float2 b10 = __half22float2(*(const __half2*)&u10.y);
    const float2 a01 = __half22float2(*(const __half2*)&u01.x);
    const float2 b01 = __half22float2(*(const __half2*)&u01.y);
    const float2 a11 = __half22float2(*(const __half2*)&u11.x);
    const float2 b11 = __half22float2(*(const __half2*)&u11.y);

    float2 s0, s1;
    s0.x = wv.x * a00.x + wv.y * a10.x + wv.z * a01.x + wv.w * a11.x;
    s0.y = wv.x * a00.y + wv.y * a10.y + wv.z * a01.y + wv.w * a11.y;
    s1.x = wv.x * b00.x + wv.y * b10.x + wv.z * b01.x + wv.w * b11.x;
    s1.y = wv.x * b00.y + wv.y * b10.y + wv.z * b01.y + wv.w * b11.y;

    const __half2 h0 = __float22half2_rn(s0);
    const __half2 h1 = __float22half2_rn(s1);

    const uint32_t off = (uint32_t)pp * 256 + bswz((uint32_t)pp, (uint32_t)lane * 8);
    *(uint2*)(abuf + off) = make_uint2(*(const uint32_t*)&h0, *(const uint32_t*)&h1);
}

// ---------------------------------------------------------------------------
// pure MMA tap: warp tile 32(M) x 64(N), K=128 (8 ksteps), low live-reg form
// ---------------------------------------------------------------------------
__device__ __forceinline__ void mma_tap_pure(uint32_t Abase, uint32_t Wbase,
                                             float (*acc)[8][4],
                                             uint32_t a_row_in_warp, uint32_t a_koff,
                                             uint32_t b_n_in_pair, uint32_t b_koff,
                                             int warp_m, int warp_n) {
#pragma unroll
    for (int k0 = 0; k0 < 8; ++k0) {
        const uint32_t kb = (uint32_t)k0 * 32;

        uint32_t a0[2], a1[2], a2[2], a3[2];
#pragma unroll
        for (int mi = 0; mi < 2; ++mi) {
            const uint32_t row = (uint32_t)(warp_m * 32 + mi * 16) + a_row_in_warp;
            const uint32_t addr = Abase + row * 256 + bswz(row, kb + a_koff);
            ldm_x4(a0[mi], a1[mi], a2[mi], a3[mi], addr);
        }

#pragma unroll
        for (int np = 0; np < 4; ++np) {
            uint32_t b0, b1, b2, b3;
            const uint32_t n = (uint32_t)(warp_n * 64 + np * 16) + b_n_in_pair;
            const uint32_t addr = Wbase + n * 256 + bswz(n, kb + b_koff);
            ldm_x4(b0, b1, b2, b3, addr);
#pragma unroll
            for (int mi = 0; mi < 2; ++mi) {
                mma_16816(acc[mi][np * 2][0], acc[mi][np * 2][1],
                          acc[mi][np * 2][2], acc[mi][np * 2][3],
                          a0[mi], a1[mi], a2[mi], a3[mi], b0, b1);
                mma_16816(acc[mi][np * 2 + 1][0], acc[mi][np * 2 + 1][1],
                          acc[mi][np * 2 + 1][2], acc[mi][np * 2 + 1][3],
                          a0[mi], a1[mi], a2[mi], a3[mi], b2, b3);
            }
        }
    }
}

// ---------------------------------------------------------------------------
// Kernel 3: warp-specialized — 16 MMA warps + 4 gather warps, 640 threads.
// ---------------------------------------------------------------------------
__global__ __launch_bounds__(NTHREADS, 1)
void sphere_hmma_kernel(const float* __restrict__ bias,
                        float* __restrict__ out) {
    extern __shared__ char dsm[];
    const uint32_t raw = smem_u32(dsm);
    const uint32_t sb  = (raw + 1023u) & ~1023u;
    char* const smp = dsm + (sb - raw);

    const int tid  = threadIdx.x;
    const int lane = tid & 31;
    const int warp = tid >> 5;          // 0..19
    const int tile = blockIdx.x;
    const int b    = tile >> 8;
    const int p0   = (tile & 255) * TILE_M;

    if (tid < 256) ((float*)(smp + SM_BIAS))[tid] = bias[tid];

    const uint2* __restrict__ xh2 =
        (const uint2*)(g_xh + (size_t)b * HW * CIN);

    const bool is_mma = (warp < 16);
    const int warp_m = warp >> 2;       // 0..3 (MMA warps)
    const int warp_n = warp & 3;        // 0..3
    const int wg     = warp - 16;       // 0..3 (gather warps)
    const int tidg   = tid - 512;       // 0..127

    float acc[2][8][4];
#pragma unroll
    for (int mi = 0; mi < 2; ++mi)
#pragma unroll
        for (int ni = 0; ni < 8; ++ni)
#pragma unroll
            for (int q = 0; q < 4; ++q) acc[mi][ni][q] = 0.0f;

    const uint32_t a_row_in_warp = (uint32_t)(lane & 15);
    const uint32_t a_koff        = (uint32_t)((lane >> 4) << 4);
    const uint32_t b_n_in_pair   = (uint32_t)(((lane >> 4) & 1) * 8 + (lane & 7));
    const uint32_t b_koff        = (uint32_t)(((lane >> 3) & 1) << 4);

    // ---- prologue: MMA warps gather A(0) (8 px each); gather warps stage W(0)
    if (is_mma) {
        const int4*   __restrict__ tI = g_tabI + p0;
        const float4* __restrict__ tW = g_tabW + p0;
#pragma unroll 2
        for (int i = 0; i < 8; ++i) {
            const int pp = i * 16 + warp;
            gather_one(xh2, smp + SM_A0, __ldg(tI + pp), __ldg(tW + pp), pp, lane);
        }
    } else {
        stageW_async_gw(sb + SM_W0, g_Wf16, tidg);
        cp_commit();
        cp_wait0();
    }
    __syncthreads();

    for (int t = 0; t < 9; ++t) {
        const int cur = t & 1;
        const uint32_t Acur = sb + (cur ? SM_A1 : SM_A0);
        const uint32_t Wcur = sb + (cur ? SM_W1 : SM_W0);
        char* const Anxt = smp + (cur ? SM_A0 : SM_A1);
        const uint32_t Wnxt = sb + (cur ? SM_W0 : SM_W1);

        if (is_mma) {
            mma_tap_pure(Acur, Wcur, acc, a_row_in_warp, a_koff,
                         b_n_in_pair, b_koff, warp_m, warp_n);
        } else if (t < 8) {
            // stage W(t+1) (async) then gather A(t+1): 32 px per gather warp
            stageW_async_gw(Wnxt, g_Wf16 + (size_t)(t + 1) * 65536, tidg);
            cp_commit();
            const int4*   __restrict__ tI = g_tabI + (t + 1) * HW + p0;
            const float4* __restrict__ tW = g_tabW + (t + 1) * HW + p0;
#pragma unroll 4
            for (int i = 0; i < 32; ++i) {
                const int pp = i * 4 + wg;
                gather_one(xh2, Anxt, __ldg(tI + pp), __ldg(tW + pp), pp, lane);
            }
            cp_wait0();
        }
        __syncthreads();
    }

    // ---- epilogue: acc -> Dsm[co][px] -> coalesced out (MMA warps only) ----
    float* Dsm = (float*)smp;
    if (is_mma) {
        const int rbase = warp_m * 32 + (lane >> 2);
        const int cbase = warp_n * 64 + 2 * (lane & 3);
#pragma unroll
        for (int mi = 0; mi < 2; ++mi) {
#pragma unroll
            for (int ni = 0; ni < 8; ++ni) {
                const int rr = rbase + mi * 16;
                const int cc = cbase + ni * 8;
                Dsm[(cc    ) * 128 + rr    ] = acc[mi][ni][0];
                Dsm[(cc + 1) * 128 + rr    ] = acc[mi][ni][1];
                Dsm[(cc    ) * 128 + rr + 8] = acc[mi][ni][2];
                Dsm[(cc + 1) * 128 + rr + 8] = acc[mi][ni][3];
            }
        }
    }
    __syncthreads();

    if (is_mma) {
        const float* bs = (const float*)(smp + SM_BIAS);
        float* ob = out + (size_t)b * COUT * HW + p0;
#pragma unroll 4
        for (int it = 0; it < 16; ++it) {
            const int co = it * 16 + warp;
            const float bv = bs[co];
            float4 v = ((const float4*)(Dsm + co * 128))[lane];
            v.x += bv; v.y += bv; v.z += bv; v.w += bv;
            ((float4*)(ob + (size_t)co * HW))[lane] = v;
        }
    }
}

// ---------------------------------------------------------------------------
extern "C" void kernel_launch(void* const* d_in, const int* in_sizes, int n_in,
                              void* d_out, int out_size) {
    const float* x      = (const float*)d_in[0];   // (4,128,128,256)
    const float* weight = (const float*)d_in[1];   // (256,128,3,3)
    const float* bias   = (const float*)d_in[2];   // (256,)
    const float* grid   = (const float*)d_in[3];   // (1,384,768,2)
    float* out = (float*)d_out;                    // (4,256,128,256)

    cudaFuncSetAttribute(sphere_hmma_kernel,
                         cudaFuncAttributeMaxDynamicSharedMemorySize, SM_TOTAL);

    {
        dim3 g(HW / 32, CIN / 32, B_);
        dim3 blk(32, 8);
        transpose_x_kernel<<<g, blk>>>(x);
    }
    weight_prep_f16_kernel<<<(9 * 256 * 128 + 255) / 256, 256>>>(weight);
    grid_prep_kernel<<<(9 * HW + 255) / 256, 256>>>(grid);
    sphere_hmma_kernel<<<NTILES, NTHREADS, SM_TOTAL>>>(bias, out);
}

// round 10
// speedup vs baseline: 2.5175x; 2.5175x over previous
#include <cuda_runtime.h>
#include <cuda_fp16.h>
#include <cstdint>
#include <math.h>

// ---------------- problem constants ----------------
#define B_   4
#define CIN  128
#define COUT 256
#define H_   128
#define W_   256
#define HW   (H_ * W_)              // 32768
#define TILE_M 64                   // pixels per CTA
#define NTILES (B_ * HW / TILE_M)   // 2048
#define NTHREADS 256                // 8 warps, 2 CTAs/SM

// ---------------- device scratch ----------------
__device__ __half g_xh[(size_t)B_ * HW * CIN];       // 32 MB (B, HW, Cin) fp16
__device__ unsigned char g_Wf16[9 * 65536];          // per tap: 256 co x 256B (128 fp16), swizzled
__device__ int4   g_tabI[9 * HW];                    // gather indices (uint2 units into g_xh)
__device__ float4 g_tabW[9 * HW];                    // bilinear weights (edge-zeroed)

// ---------------- smem layout (1024-aligned base) ----------------
#define SM_A0   0            // 64 rows x 256B = 16KB
#define SM_A1   16384        // 16KB
#define SM_W    32768        // 64KB (single buffer)
#define SM_BIAS 98304        // 1KB
#define SM_TOTAL (99328 + 1024)
// epilogue reuses [0, 64KB) as Dsm[co][px] fp32 (256 x 64)

__device__ __forceinline__ uint32_t bswz(uint32_t row, uint32_t col) {
    return col ^ ((row & 7u) << 4);
}

__device__ __forceinline__ uint32_t smem_u32(const void* p) {
    uint32_t a;
    asm("{ .reg .u64 t; cvta.to.shared.u64 t, %1; cvt.u32.u64 %0, t; }" : "=r"(a) : "l"(p));
    return a;
}

__device__ __forceinline__ void ldm_x4(uint32_t& r0, uint32_t& r1, uint32_t& r2, uint32_t& r3,
                                       uint32_t addr) {
    asm volatile("ldmatrix.sync.aligned.m8n8.x4.shared.b16 {%0,%1,%2,%3}, [%4];"
                 : "=r"(r0), "=r"(r1), "=r"(r2), "=r"(r3) : "r"(addr));
}

__device__ __forceinline__ void mma_16816(float& c0, float& c1, float& c2, float& c3,
                                          uint32_t a0, uint32_t a1, uint32_t a2, uint32_t a3,
                                          uint32_t b0, uint32_t b1) {
    asm volatile(
        "mma.sync.aligned.m16n8k16.row.col.f32.f16.f16.f32 "
        "{%0,%1,%2,%3}, {%4,%5,%6,%7}, {%8,%9}, {%0,%1,%2,%3};"
        : "+f"(c0), "+f"(c1), "+f"(c2), "+f"(c3)
        : "r"(a0), "r"(a1), "r"(a2), "r"(a3), "r"(b0), "r"(b1));
}

__device__ __forceinline__ void cp_async16(uint32_t dst, const void* src) {
    asm volatile("cp.async.cg.shared.global [%0], [%1], 16;" :: "r"(dst), "l"(src) : "memory");
}
__device__ __forceinline__ void cp_commit() {
    asm volatile("cp.async.commit_group;" ::: "memory");
}
__device__ __forceinline__ void cp_wait0() {
    asm volatile("cp.async.wait_group 0;" ::: "memory");
}

// stage a 64KB pre-swizzled W block with 256 threads, non-blocking
__device__ __forceinline__ void stageW_async(uint32_t smem_dst, const unsigned char* src, int tid) {
#pragma unroll
    for (int i = 0; i < 16; ++i) {
        cp_async16(smem_dst + i * 4096 + tid * 16, src + i * 4096 + tid * 16);
    }
}

// ---------------------------------------------------------------------------
// Kernel 1: transpose+convert x (B, Cin, H, W) fp32 -> g_xh (B, HW, Cin) fp16
// ---------------------------------------------------------------------------
__global__ void transpose_x_kernel(const float* __restrict__ x) {
    __shared__ float tile[32][33];
    const int b    = blockIdx.z;
    const int cin0 = blockIdx.y * 32;
    const int p0   = blockIdx.x * 32;
    const int tx = threadIdx.x, ty = threadIdx.y;   // 32 x 8
#pragma unroll
    for (int j = 0; j < 4; ++j)
        tile[ty + 8 * j][tx] = x[((size_t)b * CIN + (cin0 + ty + 8 * j)) * HW + (p0 + tx)];
    __syncthreads();
#pragma unroll
    for (int j = 0; j < 4; ++j)
        g_xh[((size_t)b * HW + (p0 + ty + 8 * j)) * CIN + (cin0 + tx)] =
            __float2half(tile[tx][ty + 8 * j]);
}

// ---------------------------------------------------------------------------
// Kernel 2: weight prep -> fp16 per tap, 256 co rows x 128 fp16, swizzled
// ---------------------------------------------------------------------------
__global__ void weight_prep_f16_kernel(const float* __restrict__ wsrc) {
    const int idx = blockIdx.x * 256 + threadIdx.x;   // < 9*256*128
    if (idx >= 9 * 256 * 128) return;
    const int cin = idx & 127;
    const int co  = (idx >> 7) & 255;
    const int t   = idx >> 15;
    const float v = wsrc[(co * CIN + cin) * 9 + t];
    const uint32_t off = (uint32_t)co * 256 + bswz(co, (uint32_t)cin * 2);
    *(__half*)(g_Wf16 + (size_t)t * 65536 + off) = __float2half(v);
}

// ---------------------------------------------------------------------------
// Kernel 2b: grid prep -> clamped gather indices + edge-zeroed weights
// ---------------------------------------------------------------------------
__global__ void grid_prep_kernel(const float* __restrict__ gridp) {
    const int idx = blockIdx.x * 256 + threadIdx.x;   // < 9*HW
    if (idx >= 9 * HW) return;
    const int p = idx & (HW - 1);
    const int t = idx >> 15;
    const int h = p >> 8;
    const int w = p & 255;
    const int r = t / 3;
    const int c = t - r * 3;

    const int gi = (h * 3 + r) * (W_ * 3) + (w * 3 + c);
    const float gx = gridp[2 * gi + 0];
    const float gy = gridp[2 * gi + 1];

    const float ix = ((gx + 1.0f) * (float)W_ - 1.0f) * 0.5f;
    const float iy = ((gy + 1.0f) * (float)H_ - 1.0f) * 0.5f;
    const float x0f = floorf(ix), y0f = floorf(iy);
    const float fx = ix - x0f, fy = iy - y0f;
    const int xx0 = (int)x0f, yy0 = (int)y0f;
    const int xx1 = xx0 + 1, yy1 = yy0 + 1;

    float w00 = (1.0f - fx) * (1.0f - fy);
    float w10 = fx * (1.0f - fy);
    float w01 = (1.0f - fx) * fy;
    float w11 = fx * fy;
    if (xx0 < 0 || xx0 >= W_) { w00 = 0.0f; w01 = 0.0f; }
    if (xx1 < 0 || xx1 >= W_) { w10 = 0.0f; w11 = 0.0f; }
    if (yy0 < 0 || yy0 >= H_) { w00 = 0.0f; w10 = 0.0f; }
    if (yy1 < 0 || yy1 >= H_) { w01 = 0.0f; w11 = 0.0f; }

    const int xi0 = min(max(xx0, 0), W_ - 1);
    const int xi1 = min(max(xx1, 0), W_ - 1);
    const int yi0 = min(max(yy0, 0), H_ - 1);
    const int yi1 = min(max(yy1, 0), H_ - 1);

    int4 e;
    e.x = (yi0 * W_ + xi0) * 32;
    e.y = (yi0 * W_ + xi1) * 32;
    e.z = (yi1 * W_ + xi0) * 32;
    e.w = (yi1 * W_ + xi1) * 32;
    g_tabI[idx] = e;
    g_tabW[idx] = make_float4(w00, w10, w01, w11);
}

// ---------------------------------------------------------------------------
// fused tap: 8 k-steps of warp-tile (32x64) MMA with the NEXT tap's gather
// interleaved 1 pixel per warp per k-step. 8 warps cover 64 px.
// ---------------------------------------------------------------------------
template <bool GATHER>
__device__ __forceinline__ void mma_tap_fused(
    uint32_t Abase, uint32_t Wbase, float (*acc)[8][4],
    const int4* __restrict__ tI, const float4* __restrict__ tW,
    const uint2* __restrict__ xh2, char* __restrict__ Anxt,
    uint32_t a_row_in_warp, uint32_t a_koff,
    uint32_t b_n_in_pair, uint32_t b_koff,
    int warp_m, int warp_n, int lane, int warp) {

    int4 e;
    float4 wv;
    if (GATHER) {
        e  = __ldg(tI + warp);
        wv = __ldg(tW + warp);
    }

#pragma unroll
    for (int k0 = 0; k0 < 8; ++k0) {
        // ---- issue gather LDGs for pixel (k0*8 + warp) ----
        uint2 u00, u10, u01, u11;
        if (GATHER) {
            u00 = __ldg(xh2 + e.x + lane);
            u10 = __ldg(xh2 + e.y + lane);
            u01 = __ldg(xh2 + e.z + lane);
            u11 = __ldg(xh2 + e.w + lane);
        }

        const uint32_t kb = (uint32_t)k0 * 32;

        // ---- B fragments ----
        uint32_t bfr[8][2];
#pragma unroll
        for (int np = 0; np < 4; ++np) {
            const uint32_t n = (uint32_t)(warp_n * 64 + np * 16) + b_n_in_pair;
            const uint32_t addr = Wbase + n * 256 + bswz(n, kb + b_koff);
            ldm_x4(bfr[np * 2][0], bfr[np * 2][1],
                   bfr[np * 2 + 1][0], bfr[np * 2 + 1][1], addr);
        }

        // ---- A fragments ----
        uint32_t a0[2], a1[2], a2[2], a3[2];
#pragma unroll
        for (int mi = 0; mi < 2; ++mi) {
            const uint32_t row = (uint32_t)(warp_m * 32 + mi * 16) + a_row_in_warp;
            const uint32_t addr = Abase + row * 256 + bswz(row, kb + a_koff);
            ldm_x4(a0[mi], a1[mi], a2[mi], a3[mi], addr);
        }

        // ---- prefetch next table entry ----
        int4 en;
        float4 wvn;
        if (GATHER && k0 < 7) {
            en  = __ldg(tI + (k0 + 1) * 8 + warp);
            wvn = __ldg(tW + (k0 + 1) * 8 + warp);
        }

        // ---- 16 MMAs ----
#pragma unroll
        for (int mi = 0; mi < 2; ++mi) {
#pragma unroll
            for (int ni = 0; ni < 8; ++ni) {
                mma_16816(acc[mi][ni][0], acc[mi][ni][1],
                          acc[mi][ni][2], acc[mi][ni][3],
                          a0[mi], a1[mi], a2[mi], a3[mi],
                          bfr[ni][0], bfr[ni][1]);
            }
        }

        // ---- blend + store gathered pixel ----
        if (GATHER) {
            const float2 a00 = __half22float2(*(const __half2*)&u00.x);
            const float2 b00 = __half22float2(*(const __half2*)&u00.y);
            const float2 a10 = __half22float2(*(const __half2*)&u10.x);
            const float2 b10 = __half22float2(*(const __half2*)&u10.y);
            const float2 a01 = __half22float2(*(const __half2*)&u01.x);
            const float2 b01 = __half22float2(*(const __half2*)&u01.y);
            const float2 a11 = __half22float2(*(const __half2*)&u11.x);
            const float2 b11 = __half22float2(*(const __half2*)&u11.y);

            float2 s0, s1;
            s0.x = wv.x * a00.x + wv.y * a10.x + wv.z * a01.x + wv.w * a11.x;
            s0.y = wv.x * a00.y + wv.y * a10.y + wv.z * a01.y + wv.w * a11.y;
            s1.x = wv.x * b00.x + wv.y * b10.x + wv.z * b01.x + wv.w * b11.x;
            s1.y = wv.x * b00.y + wv.y * b10.y + wv.z * b01.y + wv.w * b11.y;

            const __half2 h0 = __float22half2_rn(s0);
            const __half2 h1 = __float22half2_rn(s1);

            const int pp = k0 * 8 + warp;
            const uint32_t off = (uint32_t)pp * 256 + bswz((uint32_t)pp, (uint32_t)lane * 8);
            *(uint2*)(Anxt + off) =
                make_uint2(*(const uint32_t*)&h0, *(const uint32_t*)&h1);

            e = en;
            wv = wvn;
        }
    }
}

// ---------------------------------------------------------------------------
// Kernel 3: fused gather+mma, 256 threads / 8 warps, 2 CTAs per SM.
// ---------------------------------------------------------------------------
__global__ __launch_bounds__(NTHREADS, 2)
void sphere_hmma_kernel(const float* __restrict__ bias,
                        float* __restrict__ out) {
    extern __shared__ char dsm[];
    const uint32_t raw = smem_u32(dsm);
    const uint32_t sb  = (raw + 1023u) & ~1023u;
    char* const smp = dsm + (sb - raw);

    const int tid  = threadIdx.x;
    const int lane = tid & 31;
    const int warp = tid >> 5;          // 0..7
    const int warp_m = warp >> 2;       // 0..1
    const int warp_n = warp & 3;        // 0..3
    const int tile = blockIdx.x;
    const int b    = tile >> 9;          // 512 tiles per batch
    const int p0   = (tile & 511) * TILE_M;

    ((float*)(smp + SM_BIAS))[tid] = bias[tid];

    const uint2* __restrict__ xh2 =
        (const uint2*)(g_xh + (size_t)b * HW * CIN);

    float acc[2][8][4];
#pragma unroll
    for (int mi = 0; mi < 2; ++mi)
#pragma unroll
        for (int ni = 0; ni < 8; ++ni)
#pragma unroll
            for (int q = 0; q < 4; ++q) acc[mi][ni][q] = 0.0f;

    const uint32_t a_row_in_warp = (uint32_t)(lane & 15);
    const uint32_t a_koff        = (uint32_t)((lane >> 4) << 4);
    const uint32_t b_n_in_pair   = (uint32_t)(((lane >> 4) & 1) * 8 + (lane & 7));
    const uint32_t b_koff        = (uint32_t)(((lane >> 3) & 1) << 4);

    // ---- prologue: stage W(0) (async), gather A(0) under it ----
    stageW_async(sb + SM_W, g_Wf16, tid);
    cp_commit();
    {
        const int4*   __restrict__ tI = g_tabI + p0;
        const float4* __restrict__ tW = g_tabW + p0;
#pragma unroll 2
        for (int i = 0; i < 8; ++i) {
            const int pp = i * 8 + warp;
            const int4   e  = __ldg(tI + pp);
            const float4 wv = __ldg(tW + pp);
            const uint2 u00 = __ldg(xh2 + e.x + lane);
            const uint2 u10 = __ldg(xh2 + e.y + lane);
            const uint2 u01 = __ldg(xh2 + e.z + lane);
            const uint2 u11 = __ldg(xh2 + e.w + lane);
            const float2 a00 = __half22float2(*(const __half2*)&u00.x);
            const float2 b00 = __half22float2(*(const __half2*)&u00.y);
            const float2 a10 = __half22float2(*(const __half2*)&u10.x);
            const float2 b10 = __half22float2(*(const __half2*)&u10.y);
            const float2 a01 = __half22float2(*(const __half2*)&u01.x);
            const float2 b01 = __half22float2(*(const __half2*)&u01.y);
            const float2 a11 = __half22float2(*(const __half2*)&u11.x);
            const float2 b11 = __half22float2(*(const __half2*)&u11.y);
            float2 s0, s1;
            s0.x = wv.x * a00.x + wv.y * a10.x + wv.z * a01.x + wv.w * a11.x;
            s0.y = wv.x * a00.y + wv.y * a10.y + wv.z * a01.y + wv.w * a11.y;
            s1.x = wv.x * b00.x + wv.y * b10.x + wv.z * b01.x + wv.w * b11.x;
            s1.y = wv.x * b00.y + wv.y * b10.y + wv.z * b01.y + wv.w * b11.y;
            const __half2 h0 = __float22half2_rn(s0);
            const __half2 h1 = __float22half2_rn(s1);
            const uint32_t off = (uint32_t)pp * 256 + bswz((uint32_t)pp, (uint32_t)lane * 8);
            *(uint2*)(smp + SM_A0 + off) =
                make_uint2(*(const uint32_t*)&h0, *(const uint32_t*)&h1);
        }
    }
    cp_wait0();
    __syncthreads();

    for (int t = 0; t < 9; ++t) {
        const int cur = t & 1;
        const uint32_t Acur = sb + (cur ? SM_A1 : SM_A0);
        char* const Anxt = smp + (cur ? SM_A0 : SM_A1);

        if (t < 8) {
            mma_tap_fused<true>(Acur, sb + SM_W, acc,
                                g_tabI + (t + 1) * HW + p0,
                                g_tabW + (t + 1) * HW + p0,
                                xh2, Anxt,
                                a_row_in_warp, a_koff, b_n_in_pair, b_koff,
                                warp_m, warp_n, lane, warp);
        } else {
            mma_tap_fused<false>(Acur, sb + SM_W, acc, nullptr, nullptr,
                                 xh2, nullptr,
                                 a_row_in_warp, a_koff, b_n_in_pair, b_koff,
                                 warp_m, warp_n, lane, warp);
        }
        __syncthreads();    // reads of W(t)/A(t) done; A(t+1) written

        if (t < 8) {        // restage the single W buffer for tap t+1
            stageW_async(sb + SM_W, g_Wf16 + (size_t)(t + 1) * 65536, tid);
            cp_commit();
            cp_wait0();
            __syncthreads();
        }
    }

    // ---- epilogue: acc -> Dsm[co][px] -> coalesced out ----
    float* Dsm = (float*)smp;   // 256 x 64 fp32 = 64KB
    {
        const int rbase = warp_m * 32 + (lane >> 2);
        const int cbase = warp_n * 64 + 2 * (lane & 3);
#pragma unroll
        for (int mi = 0; mi < 2; ++mi) {
#pragma unroll
            for (int ni = 0; ni < 8; ++ni) {
                const int rr = rbase + mi * 16;
                const int cc = cbase + ni * 8;
                Dsm[(cc    ) * 64 + rr    ] = acc[mi][ni][0];
                Dsm[(cc + 1) * 64 + rr    ] = acc[mi][ni][1];
                Dsm[(cc    ) * 64 + rr + 8] = acc[mi][ni][2];
                Dsm[(cc + 1) * 64 + rr + 8] = acc[mi][ni][3];
            }
        }
    }
    __syncthreads();

    {
        const float* bs = (const float*)(smp + SM_BIAS);
        float* ob = out + (size_t)b * COUT * HW + p0;
#pragma unroll 4
        for (int it = 0; it < 16; ++it) {
            const int co = it * 16 + warp * 2 + (lane >> 4);
            const float bv = bs[co];
            float4 v = ((const float4*)(Dsm + co * 64))[lane & 15];
            v.x += bv; v.y += bv; v.z += bv; v.w += bv;
            ((float4*)(ob + (size_t)co * HW))[lane & 15] = v;
        }
    }
}

// ---------------------------------------------------------------------------
extern "C" void kernel_launch(void* const* d_in, const int* in_sizes, int n_in,
                              void* d_out, int out_size) {
    const float* x      = (const float*)d_in[0];   // (4,128,128,256)
    const float* weight = (const float*)d_in[1];   // (256,128,3,3)
    const float* bias   = (const float*)d_in[2];   // (256,)
    const float* grid   = (const float*)d_in[3];   // (1,384,768,2)
    float* out = (float*)d_out;                    // (4,256,128,256)

    cudaFuncSetAttribute(sphere_hmma_kernel,
                         cudaFuncAttributeMaxDynamicSharedMemorySize, SM_TOTAL);

    {
        dim3 g(HW / 32, CIN / 32, B_);
        dim3 blk(32, 8);
        transpose_x_kernel<<<g, blk>>>(x);
    }
    weight_prep_f16_kernel<<<(9 * 256 * 128 + 255) / 256, 256>>>(weight);
    grid_prep_kernel<<<(9 * HW + 255) / 256, 256>>>(grid);
    sphere_hmma_kernel<<<NTILES, NTHREADS, SM_TOTAL>>>(bias, out);
}

// round 11
// speedup vs baseline: 2.6440x; 1.0503x over previous
#include <cuda_runtime.h>
#include <cuda_fp16.h>
#include <cstdint>
#include <math.h>

// ---------------- problem constants ----------------
#define B_   4
#define CIN  128
#define COUT 256
#define H_   128
#define W_   256
#define HW   (H_ * W_)              // 32768
#define TILE_M 128                  // pixels per CTA
#define NTILES (B_ * HW / TILE_M)   // 1024
#define NTHREADS 512

// ---------------- device scratch ----------------
__device__ __half g_xh[(size_t)B_ * HW * CIN];       // 32 MB (B, HW, Cin) fp16
__device__ unsigned char g_Wf16[9 * 65536];          // per tap: 256 co x 256B (128 fp16), swizzled
__device__ int4   g_tabI[9 * HW];                    // gather indices (uint2 units into g_xh)
__device__ float4 g_tabW[9 * HW];                    // bilinear weights (edge-zeroed)

// ---------------- smem layout (1024-aligned base) ----------------
#define SM_A0   0            // 128 rows x 256B = 32KB
#define SM_A1   32768        // 32KB
#define SM_W0   65536        // 64KB
#define SM_W1   131072       // 64KB
#define SM_BIAS 196608       // 1KB
#define SM_TOTAL (197632 + 1024)
// epilogue reuses [0, 128KB) as Dsm[co][px] fp32

__device__ __forceinline__ uint32_t bswz(uint32_t row, uint32_t col) {
    return col ^ ((row & 7u) << 4);
}

__device__ __forceinline__ uint32_t smem_u32(const void* p) {
    uint32_t a;
    asm("{ .reg .u64 t; cvta.to.shared.u64 t, %1; cvt.u32.u64 %0, t; }" : "=r"(a) : "l"(p));
    return a;
}

__device__ __forceinline__ void ldm_x4(uint32_t& r0, uint32_t& r1, uint32_t& r2, uint32_t& r3,
                                       uint32_t addr) {
    asm volatile("ldmatrix.sync.aligned.m8n8.x4.shared.b16 {%0,%1,%2,%3}, [%4];"
                 : "=r"(r0), "=r"(r1), "=r"(r2), "=r"(r3) : "r"(addr));
}

__device__ __forceinline__ void mma_16816(float& c0, float& c1, float& c2, float& c3,
                                          uint32_t a0, uint32_t a1, uint32_t a2, uint32_t a3,
                                          uint32_t b0, uint32_t b1) {
    asm volatile(
        "mma.sync.aligned.m16n8k16.row.col.f32.f16.f16.f32 "
        "{%0,%1,%2,%3}, {%4,%5,%6,%7}, {%8,%9}, {%0,%1,%2,%3};"
        : "+f"(c0), "+f"(c1), "+f"(c2), "+f"(c3)
        : "r"(a0), "r"(a1), "r"(a2), "r"(a3), "r"(b0), "r"(b1));
}

__device__ __forceinline__ void cp_async16(uint32_t dst, const void* src) {
    asm volatile("cp.async.cg.shared.global [%0], [%1], 16;" :: "r"(dst), "l"(src) : "memory");
}
__device__ __forceinline__ void cp_commit() {
    asm volatile("cp.async.commit_group;" ::: "memory");
}
__device__ __forceinline__ void cp_wait0() {
    asm volatile("cp.async.wait_group 0;" ::: "memory");
}

// stage a 64KB pre-swizzled W block with 512 threads, non-blocking
__device__ __forceinline__ void stageW_async(uint32_t smem_dst, const unsigned char* src, int tid) {
#pragma unroll
    for (int i = 0; i < 8; ++i) {
        cp_async16(smem_dst + i * 8192 + tid * 16, src + i * 8192 + tid * 16);
    }
}

// ---------------------------------------------------------------------------
// Kernel 1: transpose+convert x (B, Cin, H, W) fp32 -> g_xh (B, HW, Cin) fp16
// ---------------------------------------------------------------------------
__global__ void transpose_x_kernel(const float* __restrict__ x) {
    __shared__ float tile[32][33];
    const int b    = blockIdx.z;
    const int cin0 = blockIdx.y * 32;
    const int p0   = blockIdx.x * 32;
    const int tx = threadIdx.x, ty = threadIdx.y;   // 32 x 8
#pragma unroll
    for (int j = 0; j < 4; ++j)
        tile[ty + 8 * j][tx] = x[((size_t)b * CIN + (cin0 + ty + 8 * j)) * HW + (p0 + tx)];
    __syncthreads();
#pragma unroll
    for (int j = 0; j < 4; ++j)
        g_xh[((size_t)b * HW + (p0 + ty + 8 * j)) * CIN + (cin0 + tx)] =
            __float2half(tile[tx][ty + 8 * j]);
}

// ---------------------------------------------------------------------------
// Kernel 2: weight prep -> fp16 per tap, 256 co rows x 128 fp16, swizzled
// ---------------------------------------------------------------------------
__global__ void weight_prep_f16_kernel(const float* __restrict__ wsrc) {
    const int idx = blockIdx.x * 256 + threadIdx.x;   // < 9*256*128
    if (idx >= 9 * 256 * 128) return;
    const int cin = idx & 127;
    const int co  = (idx >> 7) & 255;
    const int t   = idx >> 15;
    const float v = wsrc[(co * CIN + cin) * 9 + t];
    const uint32_t off = (uint32_t)co * 256 + bswz(co, (uint32_t)cin * 2);
    *(__half*)(g_Wf16 + (size_t)t * 65536 + off) = __float2half(v);
}

// ---------------------------------------------------------------------------
// Kernel 2b: grid prep -> clamped gather indices + edge-zeroed weights
// ---------------------------------------------------------------------------
__global__ void grid_prep_kernel(const float* __restrict__ gridp) {
    const int idx = blockIdx.x * 256 + threadIdx.x;   // < 9*HW
    if (idx >= 9 * HW) return;
    const int p = idx & (HW - 1);
    const int t = idx >> 15;
    const int h = p >> 8;
    const int w = p & 255;
    const int r = t / 3;
    const int c = t - r * 3;

    const int gi = (h * 3 + r) * (W_ * 3) + (w * 3 + c);
    const float gx = gridp[2 * gi + 0];
    const float gy = gridp[2 * gi + 1];

    const float ix = ((gx + 1.0f) * (float)W_ - 1.0f) * 0.5f;
    const float iy = ((gy + 1.0f) * (float)H_ - 1.0f) * 0.5f;
    const float x0f = floorf(ix), y0f = floorf(iy);
    const float fx = ix - x0f, fy = iy - y0f;
    const int xx0 = (int)x0f, yy0 = (int)y0f;
    const int xx1 = xx0 + 1, yy1 = yy0 + 1;

    float w00 = (1.0f - fx) * (1.0f - fy);
    float w10 = fx * (1.0f - fy);
    float w01 = (1.0f - fx) * fy;
    float w11 = fx * fy;
    if (xx0 < 0 || xx0 >= W_) { w00 = 0.0f; w01 = 0.0f; }
    if (xx1 < 0 || xx1 >= W_) { w10 = 0.0f; w11 = 0.0f; }
    if (yy0 < 0 || yy0 >= H_) { w00 = 0.0f; w10 = 0.0f; }
    if (yy1 < 0 || yy1 >= H_) { w01 = 0.0f; w11 = 0.0f; }

    const int xi0 = min(max(xx0, 0), W_ - 1);
    const int xi1 = min(max(xx1, 0), W_ - 1);
    const int yi0 = min(max(yy0, 0), H_ - 1);
    const int yi1 = min(max(yy1, 0), H_ - 1);

    int4 e;
    e.x = (yi0 * W_ + xi0) * 32;
    e.y = (yi0 * W_ + xi1) * 32;
    e.z = (yi1 * W_ + xi0) * 32;
    e.w = (yi1 * W_ + xi1) * 32;
    g_tabI[idx] = e;
    g_tabW[idx] = make_float4(w00, w10, w01, w11);
}

// ---------------------------------------------------------------------------
// blend 4 gathered corners -> fp16 pair, swizzled STS
// ---------------------------------------------------------------------------
__device__ __forceinline__ void blend_store(char* __restrict__ abuf,
                                            const uint2 u00, const uint2 u10,
                                            const uint2 u01, const uint2 u11,
                                            const float4 wv, int pp, int lane) {
    const float2 a00 = __half22float2(*(const __half2*)&u00.x);
    const float2 b00 = __half22float2(*(const __half2*)&u00.y);
    const float2 a10 = __half22float2(*(const __half2*)&u10.x);
    const float2 b10 = __half22float2(*(const __half2*)&u10.y);
    const float2 a01 = __half22float2(*(const __half2*)&u01.x);
    const float2 b01 = __half22float2(*(const __half2*)&u01.y);
    const float2 a11 = __half22float2(*(const __half2*)&u11.x);
    const float2 b11 = __half22float2(*(const __half2*)&u11.y);

    float2 s0, s1;
    s0.x = wv.x * a00.x + wv.y * a10.x + wv.z * a01.x + wv.w * a11.x;
    s0.y = wv.x * a00.y + wv.y * a10.y + wv.z * a01.y + wv.w * a11.y;
    s1.x = wv.x * b00.x + wv.y * b10.x + wv.z * b01.x + wv.w * b11.x;
    s1.y = wv.x * b00.y + wv.y * b10.y + wv.z * b01.y + wv.w * b11.y;

    const __half2 h0 = __float22half2_rn(s0);
    const __half2 h1 = __float22half2_rn(s1);

    const uint32_t off = (uint32_t)pp * 256 + bswz((uint32_t)pp, (uint32_t)lane * 8);
    *(uint2*)(abuf + off) = make_uint2(*(const uint32_t*)&h0, *(const uint32_t*)&h1);
}

// ---------------------------------------------------------------------------
// fused tap: 8 k-steps of warp-tile (32x64) MMA, with the NEXT tap's gather
// pipelined one k-step deep: LDGs for pixel k issued at top of k-step k,
// blended AFTER the MMAs of k-step k+1 (full k-step of latency cover).
// ---------------------------------------------------------------------------
template <bool GATHER>
__device__ __forceinline__ void mma_tap_fused(
    uint32_t Abase, uint32_t Wbase, float (*acc)[8][4],
    const int4* __restrict__ tI, const float4* __restrict__ tW,
    const uint2* __restrict__ xh2, char* __restrict__ Anxt,
    uint32_t a_row_in_warp, uint32_t a_koff,
    uint32_t b_n_in_pair, uint32_t b_koff,
    int warp_m, int warp_n, int lane, int warp) {

    int4 e_cur;
    float4 wv_cur, wv_prev;
    uint2 u00, u10, u01, u11;          // LDG results for pixel k-1 (in flight)
    if (GATHER) {
        e_cur  = __ldg(tI + warp);
        wv_cur = __ldg(tW + warp);
    }

#pragma unroll
    for (int k0 = 0; k0 < 8; ++k0) {
        // ---- issue gather LDGs for pixel (k0*16 + warp) ----
        uint2 n00, n10, n01, n11;
        if (GATHER) {
            n00 = __ldg(xh2 + e_cur.x + lane);
            n10 = __ldg(xh2 + e_cur.y + lane);
            n01 = __ldg(xh2 + e_cur.z + lane);
            n11 = __ldg(xh2 + e_cur.w + lane);
        }

        // ---- table entry for pixel k0+1 ----
        int4 e_nxt;
        float4 wv_nxt;
        if (GATHER && k0 < 7) {
            e_nxt  = __ldg(tI + (k0 + 1) * 16 + warp);
            wv_nxt = __ldg(tW + (k0 + 1) * 16 + warp);
        }

        const uint32_t kb = (uint32_t)k0 * 32;

        // ---- B fragments ----
        uint32_t bfr[8][2];
#pragma unroll
        for (int np = 0; np < 4; ++np) {
            const uint32_t n = (uint32_t)(warp_n * 64 + np * 16) + b_n_in_pair;
            const uint32_t addr = Wbase + n * 256 + bswz(n, kb + b_koff);
            ldm_x4(bfr[np * 2][0], bfr[np * 2][1],
                   bfr[np * 2 + 1][0], bfr[np * 2 + 1][1], addr);
        }

        // ---- A fragments ----
        uint32_t a0[2], a1[2], a2[2], a3[2];
#pragma unroll
        for (int mi = 0; mi < 2; ++mi) {
            const uint32_t row = (uint32_t)(warp_m * 32 + mi * 16) + a_row_in_warp;
            const uint32_t addr = Abase + row * 256 + bswz(row, kb + a_koff);
            ldm_x4(a0[mi], a1[mi], a2[mi], a3[mi], addr);
        }

        // ---- 16 MMAs ----
#pragma unroll
        for (int mi = 0; mi < 2; ++mi) {
#pragma unroll
            for (int ni = 0; ni < 8; ++ni) {
                mma_16816(acc[mi][ni][0], acc[mi][ni][1],
                          acc[mi][ni][2], acc[mi][ni][3],
                          a0[mi], a1[mi], a2[mi], a3[mi],
                          bfr[ni][0], bfr[ni][1]);
            }
        }

        // ---- blend + store pixel k0-1 (loads issued a full k-step ago) ----
        if (GATHER && k0 > 0) {
            blend_store(Anxt, u00, u10, u01, u11, wv_prev,
                        (k0 - 1) * 16 + warp, lane);
        }

        // ---- rotate pipeline state ----
        if (GATHER) {
            u00 = n00; u10 = n10; u01 = n01; u11 = n11;
            wv_prev = wv_cur;
            e_cur = e_nxt;
            wv_cur = wv_nxt;
        }
    }

    // ---- drain: blend + store pixel of k-step 7 ----
    if (GATHER) {
        blend_store(Anxt, u00, u10, u01, u11, wv_prev, 7 * 16 + warp, lane);
    }
}

// ---------------------------------------------------------------------------
// Kernel 3: fused gather+mma, 512 threads / 16 warps, warp tile 32x64
// ---------------------------------------------------------------------------
__global__ __launch_bounds__(NTHREADS, 1)
void sphere_hmma_kernel(const float* __restrict__ bias,
                        float* __restrict__ out) {
    extern __shared__ char dsm[];
    const uint32_t raw = smem_u32(dsm);
    const uint32_t sb  = (raw + 1023u) & ~1023u;
    char* const smp = dsm + (sb - raw);

    const int tid  = threadIdx.x;
    const int lane = tid & 31;
    const int warp = tid >> 5;          // 0..15
    const int warp_m = warp >> 2;       // 0..3
    const int warp_n = warp & 3;        // 0..3
    const int tile = blockIdx.x;
    const int b    = tile >> 8;
    const int p0   = (tile & 255) * TILE_M;

    if (tid < 256) ((float*)(smp + SM_BIAS))[tid] = bias[tid];

    const uint2* __restrict__ xh2 =
        (const uint2*)(g_xh + (size_t)b * HW * CIN);

    float acc[2][8][4];
#pragma unroll
    for (int mi = 0; mi < 2; ++mi)
#pragma unroll
        for (int ni = 0; ni < 8; ++ni)
#pragma unroll
            for (int q = 0; q < 4; ++q) acc[mi][ni][q] = 0.0f;

    const uint32_t a_row_in_warp = (uint32_t)(lane & 15);
    const uint32_t a_koff        = (uint32_t)((lane >> 4) << 4);
    const uint32_t b_n_in_pair   = (uint32_t)(((lane >> 4) & 1) * 8 + (lane & 7));
    const uint32_t b_koff        = (uint32_t)(((lane >> 3) & 1) << 4);

    // ---- prologue: stage W(0); gather A(0) (table-driven, unfused) ----
    stageW_async(sb + SM_W0, g_Wf16, tid);
    cp_commit();
    {
        const int4*   __restrict__ tI = g_tabI + p0;
        const float4* __restrict__ tW = g_tabW + p0;
#pragma unroll 2
        for (int i = 0; i < 8; ++i) {
            const int pp = i * 16 + warp;
            const int4   e  = __ldg(tI + pp);
            const float4 wv = __ldg(tW + pp);
            const uint2 u00 = __ldg(xh2 + e.x + lane);
            const uint2 u10 = __ldg(xh2 + e.y + lane);
            const uint2 u01 = __ldg(xh2 + e.z + lane);
            const uint2 u11 = __ldg(xh2 + e.w + lane);
            blend_store(smp + SM_A0, u00, u10, u01, u11, wv, pp, lane);
        }
    }
    cp_wait0();
    __syncthreads();

    for (int t = 0; t < 9; ++t) {
        const int cur = t & 1;
        const uint32_t Acur = sb + (cur ? SM_A1 : SM_A0);
        const uint32_t Wcur = sb + (cur ? SM_W1 : SM_W0);
        char* const Anxt = smp + (cur ? SM_A0 : SM_A1);
        const uint32_t Wnxt = sb + (cur ? SM_W0 : SM_W1);

        if (t < 8) {
            stageW_async(Wnxt, g_Wf16 + (size_t)(t + 1) * 65536, tid);
            cp_commit();
            mma_tap_fused<true>(Acur, Wcur, acc,
                                g_tabI + (t + 1) * HW + p0,
                                g_tabW + (t + 1) * HW + p0,
                                xh2, Anxt,
                                a_row_in_warp, a_koff, b_n_in_pair, b_koff,
                                warp_m, warp_n, lane, warp);
            cp_wait0();
        } else {
            mma_tap_fused<false>(Acur, Wcur, acc, nullptr, nullptr,
                                 xh2, nullptr,
                                 a_row_in_warp, a_koff, b_n_in_pair, b_koff,
                                 warp_m, warp_n, lane, warp);
        }
        __syncthreads();
    }

    // ---- epilogue: acc -> Dsm[co][px] -> coalesced out ----
    float* Dsm = (float*)smp;
    {
        const int rbase = warp_m * 32 + (lane >> 2);
        const int cbase = warp_n * 64 + 2 * (lane & 3);
#pragma unroll
        for (int mi = 0; mi < 2; ++mi) {
#pragma unroll
            for (int ni = 0; ni < 8; ++ni) {
                const int rr = rbase + mi * 16;
                const int cc = cbase + ni * 8;
                Dsm[(cc    ) * 128 + rr    ] = acc[mi][ni][0];
                Dsm[(cc + 1) * 128 + rr    ] = acc[mi][ni][1];
                Dsm[(cc    ) * 128 + rr + 8] = acc[mi][ni][2];
                Dsm[(cc + 1) * 128 + rr + 8] = acc[mi][ni][3];
            }
        }
    }
    __syncthreads();

    {
        const float* bs = (const float*)(smp + SM_BIAS);
        float* ob = out + (size_t)b * COUT * HW + p0;
#pragma unroll 4
        for (int it = 0; it < 16; ++it) {
            const int co = it * 16 + warp;
            const float bv = bs[co];
            float4 v = ((const float4*)(Dsm + co * 128))[lane];
            v.x += bv; v.y += bv; v.z += bv; v.w += bv;
            ((float4*)(ob + (size_t)co * HW))[lane] = v;
        }
    }
}

// ---------------------------------------------------------------------------
extern "C" void kernel_launch(void* const* d_in, const int* in_sizes, int n_in,
                              void* d_out, int out_size) {
    const float* x      = (const float*)d_in[0];   // (4,128,128,256)
    const float* weight = (const float*)d_in[1];   // (256,128,3,3)
    const float* bias   = (const float*)d_in[2];   // (256,)
    const float* grid   = (const float*)d_in[3];   // (1,384,768,2)
    float* out = (float*)d_out;                    // (4,256,128,256)

    cudaFuncSetAttribute(sphere_hmma_kernel,
                         cudaFuncAttributeMaxDynamicSharedMemorySize, SM_TOTAL);

    {
        dim3 g(HW / 32, CIN / 32, B_);
        dim3 blk(32, 8);
        transpose_x_kernel<<<g, blk>>>(x);
    }
    weight_prep_f16_kernel<<<(9 * 256 * 128 + 255) / 256, 256>>>(weight);
    grid_prep_kernel<<<(9 * HW + 255) / 256, 256>>>(grid);
    sphere_hmma_kernel<<<NTILES, NTHREADS, SM_TOTAL>>>(bias, out);
}